// round 2
// baseline (speedup 1.0000x reference)
#include <cuda_runtime.h>
#include <cuda_bf16.h>

#define BB 2
#define NN 64
#define NGTK 8
#define CC 17
#define HWSZ 4096
#define S_TILES 8
#define TILE (HWSZ / S_TILES)   /* 512 */
#define TP2 (TILE / 2)          /* 256 element-pairs per tile */

// Scratch (device globals — no runtime allocation allowed)
__device__ int    g_peak[BB * NGTK * CC];
__device__ float  g_valid[BB * NGTK * CC];
__device__ float  g_accm[BB * NN * NGTK];

// packed f32x2 FMA (FFMA2) — only reachable via PTX on sm_103a
#define FMA2(acc, ab, cd) \
    asm("fma.rn.f32x2 %0, %1, %2, %3;" : "=l"(acc) : "l"(ab), "l"(cd), "l"(acc))

#define PACK2(out, lo, hi) \
    asm("mov.b64 %0, {%1, %2};" : "=l"(out) : "f"(lo), "f"(hi))

#define UNPACK2(lo, hi, in) \
    asm("mov.b64 {%0, %1}, %2;" : "=f"(lo), "=f"(hi) : "l"(in))

// ---------------------------------------------------------------------------
// Per (b,g,c): validity flag + peak index. Block 0 also zeroes g_accm.
__global__ void prep_kernel(const float* __restrict__ gt) {
    int bgc = blockIdx.x;   // = b*NGTK*CC + g*CC + c  (matches gt linearization)
    const float* src = gt + (size_t)bgc * HWSZ;

    if (blockIdx.x == 0) {
        for (int i = threadIdx.x; i < BB * NN * NGTK; i += blockDim.x)
            g_accm[i] = 0.0f;
    }

    float s = 0.0f;
    int pk = -1;
    for (int i = threadIdx.x; i < HWSZ; i += blockDim.x) {
        float t = src[i];
        s += t;
        if (t == 1.0f) pk = i;
    }
    for (int o = 16; o > 0; o >>= 1) {
        s += __shfl_xor_sync(0xffffffffu, s, o);
        pk = max(pk, __shfl_xor_sync(0xffffffffu, pk, o));
    }
    __shared__ float ws[8];
    __shared__ int   wp[8];
    int w = threadIdx.x >> 5;
    if ((threadIdx.x & 31) == 0) { ws[w] = s; wp[w] = pk; }
    __syncthreads();
    if (threadIdx.x == 0) {
        float tot = 0.0f; int p = -1;
        int nw = blockDim.x >> 5;
        for (int i = 0; i < nw; i++) { tot += ws[i]; p = max(p, wp[i]); }
        g_valid[bgc] = (tot != 0.0f) ? 1.0f : 0.0f;
        g_peak[bgc]  = p;
    }
}

// ---------------------------------------------------------------------------
// A2 = softplus(x)*p^2 ; nX2 = -(x*p^2),  p = sigmoid(x)
__device__ __forceinline__ void ph_pre(float x, float& A2, float& nX2) {
    float e  = __expf(-fabsf(x));
    float r  = __fdividef(1.0f, 1.0f + e);
    float p  = (x >= 0.0f) ? r : 1.0f - r;          // sigmoid(x)
    float a  = fmaxf(x, 0.0f) + __logf(1.0f + e);   // softplus(x)
    float p2 = p * p;
    A2  = a * p2;
    nX2 = -(x * p2);
}

// Dense focal-cost accumulation + fused peak correction.
// grid = (S_TILES, CC, BB), 256 threads (8 warps).
// Warp w handles preds n = w*8 + rep*4 + u  (rep in 0..1, u in 0..3).
__global__ __launch_bounds__(256, 2) void dense_kernel(const float* __restrict__ ph,
                                                       const float* __restrict__ gt) {
    int s = blockIdx.x, c = blockIdx.y, b = blockIdx.z;

    __shared__ float4 sg[NGTK][TP2];   // (c2_e, c2_o, d2_e, d2_o) per pair — 32 KB
    __shared__ float s_pvalid[NGTK];
    __shared__ int   s_peak[NGTK];

    if (threadIdx.x < NGTK) {
        int idx = (b * NGTK + threadIdx.x) * CC + c;
        s_pvalid[threadIdx.x] = g_valid[idx];
        s_peak[threadIdx.x]   = g_peak[idx];
    }
    __syncthreads();

    // fill smem: recompute c2 = valid*(1-t)^4, d2 = t*c2 from gt directly
    {
        int tid = threadIdx.x;  // 0..255 = pair index
#pragma unroll
        for (int g = 0; g < NGTK; ++g) {
            const float2* gsrc = reinterpret_cast<const float2*>(
                gt + ((size_t)(b * NGTK + g) * CC + c) * HWSZ + (size_t)s * TILE);
            float2 tv = gsrc[tid];
            float v = s_pvalid[g];
            float om0 = 1.0f - tv.x, om1 = 1.0f - tv.y;
            float w0 = om0 * om0,    w1 = om1 * om1;
            float c20 = v * w0 * w0, c21 = v * w1 * w1;
            sg[g][tid] = make_float4(c20, c21, tv.x * c20, tv.y * c21);
        }
    }
    __syncthreads();

    int w = threadIdx.x >> 5, L = threadIdx.x & 31;
    const float* phb = ph + ((size_t)b * NN * CC + c) * HWSZ + (size_t)s * TILE;
    int lo_bound = s * TILE;

    for (int rep = 0; rep < 2; ++rep) {
        int n0 = w * 8 + rep * 4;
        unsigned long long acc[4][NGTK];
#pragma unroll
        for (int u = 0; u < 4; u++)
#pragma unroll
            for (int g = 0; g < NGTK; g++) acc[u][g] = 0ULL;

#pragma unroll
        for (int i = 0; i < TP2 / 32; i++) {   // 8 iterations
            int ep = L + 32 * i;               // element-pair index
            unsigned long long A2p[4], nX2p[4];
#pragma unroll
            for (int u = 0; u < 4; u++) {
                float2 xv = *reinterpret_cast<const float2*>(
                    phb + (size_t)(n0 + u) * CC * HWSZ + 2 * ep);
                float a0, n0x, a1, n1x;
                ph_pre(xv.x, a0, n0x);
                ph_pre(xv.y, a1, n1x);
                PACK2(A2p[u],  a0,  a1);
                PACK2(nX2p[u], n0x, n1x);
            }
#pragma unroll
            for (int g = 0; g < NGTK; g++) {
                ulonglong2 ct = *reinterpret_cast<const ulonglong2*>(&sg[g][ep]);
#pragma unroll
                for (int u = 0; u < 4; u++) {
                    FMA2(acc[u][g], A2p[u],  ct.x);   // + A2 * c2
                    FMA2(acc[u][g], nX2p[u], ct.y);   // - X2 * d2
                }
            }
        }

        // fused peak correction: lane L < 8 handles gt g = L
        float pcorr[4] = {0.0f, 0.0f, 0.0f, 0.0f};
        if (L < NGTK) {
            int pk = s_peak[L];
            if (s_pvalid[L] > 0.0f && pk >= lo_bound && pk < lo_bound + TILE) {
                int off = pk - lo_bound;
#pragma unroll
                for (int u = 0; u < 4; u++) {
                    float x = phb[(size_t)(n0 + u) * CC * HWSZ + off];
                    float e = __expf(-fabsf(x));
                    float r = __fdividef(1.0f, 1.0f + e);
                    float p = (x >= 0.0f) ? r : 1.0f - r;
                    float a = fmaxf(x, 0.0f) + __logf(1.0f + e);
                    float q = 1.0f - p;
                    pcorr[u] = (a - x) * q * q;   // ce * (1-p)^2 at t==1
                }
            }
        }

        // butterfly warp reduction; lane (u*8+g) commits its value
#pragma unroll
        for (int u = 0; u < 4; u++) {
#pragma unroll
            for (int g = 0; g < NGTK; g++) {
                float vlo, vhi;
                UNPACK2(vlo, vhi, acc[u][g]);
                float v = vlo + vhi;
                if (L == g) v += pcorr[u];
                v += __shfl_xor_sync(0xffffffffu, v, 16);
                v += __shfl_xor_sync(0xffffffffu, v, 8);
                v += __shfl_xor_sync(0xffffffffu, v, 4);
                v += __shfl_xor_sync(0xffffffffu, v, 2);
                v += __shfl_xor_sync(0xffffffffu, v, 1);
                if (L == u * NGTK + g)
                    atomicAdd(&g_accm[(b * NN + n0 + u) * NGTK + g], v);
            }
        }
    }
}

// ---------------------------------------------------------------------------
__device__ __forceinline__ float fast_sigmoid(float x) {
    float e = __expf(-fabsf(x));
    float r = __fdividef(1.0f, 1.0f + e);
    return (x >= 0.0f) ? r : 1.0f - r;
}

// One thread per (b,n,g). 4 blocks x 256 threads = 1024 threads. No ph access.
__global__ void finalize_kernel(const float* __restrict__ ps,
                                const float* __restrict__ po,
                                const float* __restrict__ go,
                                float* __restrict__ out) {
    int idx = blockIdx.x * blockDim.x + threadIdx.x;
    if (idx >= BB * NN * NGTK) return;
    int g = idx & (NGTK - 1);
    int n = (idx >> 3) & (NN - 1);
    int b = idx >> 9;

    float offacc = 0.0f, vcnt = 0.0f;
#pragma unroll
    for (int c = 0; c < CC; c++) {
        int vi = (b * NGTK + g) * CC + c;
        float v = g_valid[vi];
        float2 pov = *reinterpret_cast<const float2*>(po + ((size_t)(b * NN + n) * CC + c) * 2);
        float2 gov = *reinterpret_cast<const float2*>(go + (size_t)vi * 2);
        float s0 = fast_sigmoid(pov.x) - gov.x;
        float s1 = fast_sigmoid(pov.y) - gov.y;
        offacc += v * (s0 * s0 + s1 * s1);
        vcnt   += v;
    }
    float nk  = fmaxf(vcnt, 1.0f);
    float inv = __fdividef(1.0f, nk);

    // score cost: ALPHA * bce(x,1) * (1-sigmoid(x))^2
    float x = ps[b * NN + n];
    float e = __expf(-fabsf(x));
    float r = __fdividef(1.0f, 1.0f + e);
    float sp = (x >= 0.0f) ? r : 1.0f - r;
    float bce1 = fmaxf(x, 0.0f) - x + __logf(1.0f + e);
    float q = 1.0f - sp;
    float ssc = 0.25f * bce1 * q * q;

    float hms = g_accm[(b * NN + n) * NGTK + g] * inv;   // peak corr already fused
    float off = offacc * inv * 0.5f;
    out[(b * NN + n) * NGTK + g] = 2.0f * hms + ssc + off;  // HMS_W=2, SCORE_W=1, OFF_W=1
}

// ---------------------------------------------------------------------------
extern "C" void kernel_launch(void* const* d_in, const int* in_sizes, int n_in,
                              void* d_out, int out_size) {
    const float *ph = nullptr, *gt = nullptr, *ps = nullptr, *po = nullptr, *go = nullptr;
    for (int i = 0; i < n_in; i++) {
        switch (in_sizes[i]) {
            case BB * NN * CC * HWSZ:   ph = (const float*)d_in[i]; break;  // 8,912,896
            case BB * NGTK * CC * HWSZ: gt = (const float*)d_in[i]; break;  // 1,114,112
            case BB * NN:               ps = (const float*)d_in[i]; break;  // 128
            case BB * NN * CC * 2:      po = (const float*)d_in[i]; break;  // 4,352
            case BB * NGTK * CC * 2:    go = (const float*)d_in[i]; break;  // 544
            default: break;
        }
    }
    float* out = (float*)d_out;

    prep_kernel<<<BB * NGTK * CC, 256>>>(gt);
    dense_kernel<<<dim3(S_TILES, CC, BB), 256>>>(ph, gt);
    finalize_kernel<<<4, 256>>>(ps, po, go, out);
}

// round 3
// speedup vs baseline: 1.0068x; 1.0068x over previous
#include <cuda_runtime.h>
#include <cuda_bf16.h>

#define BB 2
#define NN 64
#define NGTK 8
#define CC 17
#define HWSZ 4096
#define S_TILES 8
#define TILE (HWSZ / S_TILES)   /* 512 */
#define TP2 (TILE / 2)          /* 256 element-pairs per tile */

// Scratch (device globals — no runtime allocation allowed)
__device__ int    g_peak[BB * NGTK * CC];
__device__ float  g_valid[BB * NGTK * CC];
__device__ float  g_accm[BB * NN * NGTK];

// ---------------------------------------------------------------------------
// Per (b,g,c): validity flag + peak index, vectorized float4 loads.
// Block 0 also zeroes g_accm.
__global__ void prep_kernel(const float* __restrict__ gt) {
    int bgc = blockIdx.x;   // = b*NGTK*CC + g*CC + c  (matches gt linearization)
    const float4* src = reinterpret_cast<const float4*>(gt + (size_t)bgc * HWSZ);

    if (blockIdx.x == 0) {
        for (int i = threadIdx.x; i < BB * NN * NGTK; i += blockDim.x)
            g_accm[i] = 0.0f;
    }

    float s = 0.0f;
    int pk = -1;
#pragma unroll
    for (int j = 0; j < 4; j++) {
        int vi = threadIdx.x + 256 * j;          // float4 index, 0..1023
        float4 v = src[vi];
        s += (v.x + v.y) + (v.z + v.w);
        int base = 4 * vi;
        if (v.x == 1.0f) pk = base;
        if (v.y == 1.0f) pk = base + 1;
        if (v.z == 1.0f) pk = base + 2;
        if (v.w == 1.0f) pk = base + 3;
    }
    for (int o = 16; o > 0; o >>= 1) {
        s += __shfl_xor_sync(0xffffffffu, s, o);
        pk = max(pk, __shfl_xor_sync(0xffffffffu, pk, o));
    }
    __shared__ float ws[8];
    __shared__ int   wp[8];
    int w = threadIdx.x >> 5;
    if ((threadIdx.x & 31) == 0) { ws[w] = s; wp[w] = pk; }
    __syncthreads();
    if (threadIdx.x == 0) {
        float tot = 0.0f; int p = -1;
#pragma unroll
        for (int i = 0; i < 8; i++) { tot += ws[i]; p = max(p, wp[i]); }
        g_valid[bgc] = (tot != 0.0f) ? 1.0f : 0.0f;
        g_peak[bgc]  = p;
    }
}

// ---------------------------------------------------------------------------
// A2 = softplus(x)*p^2 ; nX2 = -(x*p^2),  p = sigmoid(x)
__device__ __forceinline__ void ph_pre(float x, float& A2, float& nX2) {
    float e  = __expf(-fabsf(x));
    float r  = __fdividef(1.0f, 1.0f + e);
    float p  = (x >= 0.0f) ? r : 1.0f - r;          // sigmoid(x)
    float a  = fmaxf(x, 0.0f) + __logf(1.0f + e);   // softplus(x)
    float p2 = p * p;
    A2  = a * p2;
    nX2 = -(x * p2);
}

// Dense focal-cost accumulation + fused peak correction.
// grid = (S_TILES, CC, BB), 256 threads (8 warps), 3 blocks/SM target.
// Warp w handles preds n = w*8 + rep*4 + u  (rep in 0..1, u in 0..3).
__global__ __launch_bounds__(256, 3) void dense_kernel(const float* __restrict__ ph,
                                                       const float* __restrict__ gt) {
    int s = blockIdx.x, c = blockIdx.y, b = blockIdx.z;

    __shared__ float4 sg[NGTK][TP2];   // (c2_e, c2_o, d2_e, d2_o) per pair — 32 KB
    __shared__ float s_pvalid[NGTK];
    __shared__ int   s_peak[NGTK];

    if (threadIdx.x < NGTK) {
        int idx = (b * NGTK + threadIdx.x) * CC + c;
        s_pvalid[threadIdx.x] = g_valid[idx];
        s_peak[threadIdx.x]   = g_peak[idx];
    }
    __syncthreads();

    // fill smem: recompute c2 = valid*(1-t)^4, d2 = t*c2 from gt directly
    {
        int tid = threadIdx.x;  // 0..255 = pair index
#pragma unroll
        for (int g = 0; g < NGTK; ++g) {
            const float2* gsrc = reinterpret_cast<const float2*>(
                gt + ((size_t)(b * NGTK + g) * CC + c) * HWSZ + (size_t)s * TILE);
            float2 tv = gsrc[tid];
            float v = s_pvalid[g];
            float om0 = 1.0f - tv.x, om1 = 1.0f - tv.y;
            float w0 = om0 * om0,    w1 = om1 * om1;
            float c20 = v * w0 * w0, c21 = v * w1 * w1;
            sg[g][tid] = make_float4(c20, c21, tv.x * c20, tv.y * c21);
        }
    }
    __syncthreads();

    int w = threadIdx.x >> 5, L = threadIdx.x & 31;
    const float* phb = ph + ((size_t)b * NN * CC + c) * HWSZ + (size_t)s * TILE;
    int lo_bound = s * TILE;

    for (int rep = 0; rep < 2; ++rep) {
        int n0 = w * 8 + rep * 4;

        const float2* pp[4];
#pragma unroll
        for (int u = 0; u < 4; u++)
            pp[u] = reinterpret_cast<const float2*>(phb + (size_t)(n0 + u) * CC * HWSZ);

        float acc[4][NGTK];
#pragma unroll
        for (int u = 0; u < 4; u++)
#pragma unroll
            for (int g = 0; g < NGTK; g++) acc[u][g] = 0.0f;

        // prefetch iteration 0
        float2 xv_cur[4];
#pragma unroll
        for (int u = 0; u < 4; u++) xv_cur[u] = pp[u][L];

#pragma unroll
        for (int i = 0; i < TP2 / 32; i++) {   // 8 iterations
            int ep = L + 32 * i;               // element-pair index

            // prefetch next iteration's ph values (hides DRAM latency)
            float2 xv_nxt[4];
            if (i < TP2 / 32 - 1) {
#pragma unroll
                for (int u = 0; u < 4; u++) xv_nxt[u] = pp[u][ep + 32];
            }

            float A2[4][2], nX2[4][2];
#pragma unroll
            for (int u = 0; u < 4; u++) {
                ph_pre(xv_cur[u].x, A2[u][0], nX2[u][0]);
                ph_pre(xv_cur[u].y, A2[u][1], nX2[u][1]);
            }
#pragma unroll
            for (int g = 0; g < NGTK; g++) {
                float4 ct = sg[g][ep];
#pragma unroll
                for (int u = 0; u < 4; u++) {
                    float t = acc[u][g];
                    t = fmaf(A2[u][0],  ct.x, t);
                    t = fmaf(nX2[u][0], ct.z, t);
                    t = fmaf(A2[u][1],  ct.y, t);
                    t = fmaf(nX2[u][1], ct.w, t);
                    acc[u][g] = t;
                }
            }
#pragma unroll
            for (int u = 0; u < 4; u++) xv_cur[u] = xv_nxt[u];
        }

        // fused peak correction: lane L < 8 handles gt g = L
        float pcorr[4] = {0.0f, 0.0f, 0.0f, 0.0f};
        if (L < NGTK) {
            int pk = s_peak[L];
            if (s_pvalid[L] > 0.0f && pk >= lo_bound && pk < lo_bound + TILE) {
                int off = pk - lo_bound;
#pragma unroll
                for (int u = 0; u < 4; u++) {
                    float x = phb[(size_t)(n0 + u) * CC * HWSZ + off];
                    float e = __expf(-fabsf(x));
                    float r = __fdividef(1.0f, 1.0f + e);
                    float p = (x >= 0.0f) ? r : 1.0f - r;
                    float a = fmaxf(x, 0.0f) + __logf(1.0f + e);
                    float q = 1.0f - p;
                    pcorr[u] = (a - x) * q * q;   // ce * (1-p)^2 at t==1
                }
            }
        }

        // butterfly warp reduction; lane (u*8+g) commits its value
#pragma unroll
        for (int u = 0; u < 4; u++) {
#pragma unroll
            for (int g = 0; g < NGTK; g++) {
                float v = acc[u][g];
                if (L == g) v += pcorr[u];
                v += __shfl_xor_sync(0xffffffffu, v, 16);
                v += __shfl_xor_sync(0xffffffffu, v, 8);
                v += __shfl_xor_sync(0xffffffffu, v, 4);
                v += __shfl_xor_sync(0xffffffffu, v, 2);
                v += __shfl_xor_sync(0xffffffffu, v, 1);
                if (L == u * NGTK + g)
                    atomicAdd(&g_accm[(b * NN + n0 + u) * NGTK + g], v);
            }
        }
    }
}

// ---------------------------------------------------------------------------
__device__ __forceinline__ float fast_sigmoid(float x) {
    float e = __expf(-fabsf(x));
    float r = __fdividef(1.0f, 1.0f + e);
    return (x >= 0.0f) ? r : 1.0f - r;
}

// One thread per (b,n,g). 4 blocks x 256 threads = 1024 threads. No ph access.
__global__ void finalize_kernel(const float* __restrict__ ps,
                                const float* __restrict__ po,
                                const float* __restrict__ go,
                                float* __restrict__ out) {
    int idx = blockIdx.x * blockDim.x + threadIdx.x;
    if (idx >= BB * NN * NGTK) return;
    int g = idx & (NGTK - 1);
    int n = (idx >> 3) & (NN - 1);
    int b = idx >> 9;

    float offacc = 0.0f, vcnt = 0.0f;
#pragma unroll
    for (int c = 0; c < CC; c++) {
        int vi = (b * NGTK + g) * CC + c;
        float v = g_valid[vi];
        float2 pov = *reinterpret_cast<const float2*>(po + ((size_t)(b * NN + n) * CC + c) * 2);
        float2 gov = *reinterpret_cast<const float2*>(go + (size_t)vi * 2);
        float s0 = fast_sigmoid(pov.x) - gov.x;
        float s1 = fast_sigmoid(pov.y) - gov.y;
        offacc += v * (s0 * s0 + s1 * s1);
        vcnt   += v;
    }
    float nk  = fmaxf(vcnt, 1.0f);
    float inv = __fdividef(1.0f, nk);

    // score cost: ALPHA * bce(x,1) * (1-sigmoid(x))^2
    float x = ps[b * NN + n];
    float e = __expf(-fabsf(x));
    float r = __fdividef(1.0f, 1.0f + e);
    float sp = (x >= 0.0f) ? r : 1.0f - r;
    float bce1 = fmaxf(x, 0.0f) - x + __logf(1.0f + e);
    float q = 1.0f - sp;
    float ssc = 0.25f * bce1 * q * q;

    float hms = g_accm[(b * NN + n) * NGTK + g] * inv;   // peak corr already fused
    float off = offacc * inv * 0.5f;
    out[(b * NN + n) * NGTK + g] = 2.0f * hms + ssc + off;  // HMS_W=2, SCORE_W=1, OFF_W=1
}

// ---------------------------------------------------------------------------
extern "C" void kernel_launch(void* const* d_in, const int* in_sizes, int n_in,
                              void* d_out, int out_size) {
    const float *ph = nullptr, *gt = nullptr, *ps = nullptr, *po = nullptr, *go = nullptr;
    for (int i = 0; i < n_in; i++) {
        switch (in_sizes[i]) {
            case BB * NN * CC * HWSZ:   ph = (const float*)d_in[i]; break;  // 8,912,896
            case BB * NGTK * CC * HWSZ: gt = (const float*)d_in[i]; break;  // 1,114,112
            case BB * NN:               ps = (const float*)d_in[i]; break;  // 128
            case BB * NN * CC * 2:      po = (const float*)d_in[i]; break;  // 4,352
            case BB * NGTK * CC * 2:    go = (const float*)d_in[i]; break;  // 544
            default: break;
        }
    }
    float* out = (float*)d_out;

    prep_kernel<<<BB * NGTK * CC, 256>>>(gt);
    dense_kernel<<<dim3(S_TILES, CC, BB), 256>>>(ph, gt);
    finalize_kernel<<<4, 256>>>(ps, po, go, out);
}